// round 8
// baseline (speedup 1.0000x reference)
#include <cuda_runtime.h>
#include <cuda_bf16.h>

#define NEGV (-10000.0f)
#define W 2048
#define H 2048
#define RPB 256
#define TPB 256

__device__ __forceinline__ float4 max4(float4 a, float4 b) {
    return make_float4(fmaxf(a.x, b.x), fmaxf(a.y, b.y), fmaxf(a.z, b.z), fmaxf(a.w, b.w));
}
__device__ __forceinline__ float4 max4_3(float4 a, float4 b, float4 c) {
    return max4(max4(a, b), c);
}

// Horizontal 5-tap max over cols f0..f7 = [col0-2 .. col0+5] -> 4 outputs.
__device__ __forceinline__ float4 hmax(float2 l, float4 c, float2 r) {
    float f0 = l.x, f1 = l.y, f2 = c.x, f3 = c.y, f4 = c.z, f5 = c.w, f6 = r.x, f7 = r.y;
    float p0 = fmaxf(f0, f1);
    float p1 = fmaxf(f1, f2);
    float p2 = fmaxf(f2, f3);
    float p3 = fmaxf(f3, f4);
    float p4 = fmaxf(f4, f5);
    float p5 = fmaxf(f5, f6);
    return make_float4(fmaxf(fmaxf(p0, p2), f4),
                       fmaxf(fmaxf(p1, p3), f5),
                       fmaxf(fmaxf(p2, p4), f6),
                       fmaxf(fmaxf(p3, p5), f7));
}

// 3 independent, always-in-bounds loads; edge patch via FSEL only.
__device__ __forceinline__ float4 loadrow(const float* __restrict__ rp,
                                          int loff, int roff, bool hl, bool hr) {
    float4 c = *reinterpret_cast<const float4*>(rp);
    float2 l = *reinterpret_cast<const float2*>(rp + loff);
    float2 r = *reinterpret_cast<const float2*>(rp + roff);
    if (!hl) { l.x = NEGV; l.y = NEGV; }
    if (!hr) { r.x = NEGV; r.y = NEGV; }
    return hmax(l, c, r);
}

template <bool CT, bool CB>
__device__ __forceinline__ void strip(const float* __restrict__ pin,
                                      float* __restrict__ pout,
                                      int y0, int col0) {
    const bool hl = col0 > 0;
    const bool hr = col0 + 4 < W;
    const int loff = hl ? -2 : 0;   // clamped: still in-bounds at the edge
    const int roff = hr ? 4 : 0;

    const float* p  = pin  + (size_t)y0 * W + col0;
    float*       po = pout + (size_t)y0 * W + col0;

    // Ring: h0..h3 = hmax of rows y-2 .. y+1
    float4 h0, h1, h2, h3;
    if (CT) {
        h0 = make_float4(NEGV, NEGV, NEGV, NEGV);
        h1 = h0;
    } else {
        h0 = loadrow(p - 2 * W, loff, roff, hl, hr);
        h1 = loadrow(p - 1 * W, loff, roff, hl, hr);
    }
    h2 = loadrow(p,     loff, roff, hl, hr);
    h3 = loadrow(p + W, loff, roff, hl, hr);

    const float* pl = p + 2 * W;            // row y+2
    const int nIter = CB ? (RPB / 4 - 1) : (RPB / 4);

    #pragma unroll 2
    for (int i = 0; i < nIter; ++i) {
        // 12 independent loads, issued with no intervening control flow.
        float4 m0 = loadrow(pl,         loff, roff, hl, hr);   // row y+2
        float4 m1 = loadrow(pl + W,     loff, roff, hl, hr);   // row y+3
        float4 m2 = loadrow(pl + 2 * W, loff, roff, hl, hr);   // row y+4
        float4 m3 = loadrow(pl + 3 * W, loff, roff, hl, hr);   // row y+5
        pl += 4 * W;

        // Shared vertical-max subexpressions.
        float4 a = max4(h2, h3);
        float4 b = max4(m0, m1);
        float4 c = max4(m2, m3);

        float4 o0 = max4_3(max4(h0, h1), a, m0);  // out y
        float4 o1 = max4_3(h1, a, b);             // out y+1
        float4 o2 = max4_3(a, b, m2);             // out y+2
        float4 o3 = max4_3(h3, b, c);             // out y+3

        __stcs(reinterpret_cast<float4*>(po),         o0);
        __stcs(reinterpret_cast<float4*>(po + W),     o1);
        __stcs(reinterpret_cast<float4*>(po + 2 * W), o2);
        __stcs(reinterpret_cast<float4*>(po + 3 * W), o3);
        po += 4 * W;

        h0 = m0; h1 = m1; h2 = m2; h3 = m3;
    }

    if (CB) {
        // Last 4 rows (H-4..H-1). Rows H, H+1 are pad (NEGV) and never win.
        float4 m0 = loadrow(pl,     loff, roff, hl, hr);       // row H-2
        float4 m1 = loadrow(pl + W, loff, roff, hl, hr);       // row H-1

        float4 a = max4(h2, h3);
        float4 b = max4(m0, m1);

        float4 o0 = max4_3(max4(h0, h1), a, m0);  // out H-4
        float4 o1 = max4_3(h1, a, b);             // out H-3
        float4 o2 = max4(a, b);                   // out H-2
        float4 o3 = max4(h3, b);                  // out H-1

        __stcs(reinterpret_cast<float4*>(po),         o0);
        __stcs(reinterpret_cast<float4*>(po + W),     o1);
        __stcs(reinterpret_cast<float4*>(po + 2 * W), o2);
        __stcs(reinterpret_cast<float4*>(po + 3 * W), o3);
    }
}

__global__ __launch_bounds__(TPB)
void dilation5x5_kernel(const float* __restrict__ in, float* __restrict__ out) {
    const int col0 = 4 * (blockIdx.x * TPB + threadIdx.x);
    const size_t plane_off = (size_t)blockIdx.z * (size_t)H * (size_t)W;
    const int y0 = blockIdx.y * RPB;

    const float* __restrict__ pin  = in  + plane_off;
    float* __restrict__       pout = out + plane_off;

    if (blockIdx.y == 0)
        strip<true, false>(pin, pout, y0, col0);
    else if (blockIdx.y == gridDim.y - 1)
        strip<false, true>(pin, pout, y0, col0);
    else
        strip<false, false>(pin, pout, y0, col0);
}

extern "C" void kernel_launch(void* const* d_in, const int* in_sizes, int n_in,
                              void* d_out, int out_size) {
    const float* image = (const float*)d_in[0];
    // d_in[1] is the all-ones 5x5 SE: neigh offsets are 0, so this is exactly a
    // 5x5 sliding max with -1e4 padding (pad never beats interior values >= 0).
    float* out = (float*)d_out;

    dim3 block(TPB, 1, 1);
    dim3 grid(W / (4 * TPB), H / RPB, 24);  // 2 x 8 x 24 = 384 blocks -> one resident wave
    dilation5x5_kernel<<<grid, block>>>(image, out);
}

// round 9
// speedup vs baseline: 1.2197x; 1.2197x over previous
#include <cuda_runtime.h>
#include <cuda_bf16.h>

#define NEGV (-10000.0f)
#define W 2048
#define H 2048
#define RPB 256
#define TPB 256
#define STAGES 8
#define SROW 1040      // floats per stage (1032 used + pad)
#define BCOLS 1024     // output cols per block

__device__ __forceinline__ float4 max4(float4 a, float4 b) {
    return make_float4(fmaxf(a.x, b.x), fmaxf(a.y, b.y), fmaxf(a.z, b.z), fmaxf(a.w, b.w));
}

// Horizontal 5-tap max over f0..f7 = cols [col0-2 .. col0+5] -> 4 outputs.
__device__ __forceinline__ float4 hmax(float2 l, float4 c, float2 r) {
    float f0 = l.x, f1 = l.y, f2 = c.x, f3 = c.y, f4 = c.z, f5 = c.w, f6 = r.x, f7 = r.y;
    float p0 = fmaxf(f0, f1);
    float p1 = fmaxf(f1, f2);
    float p2 = fmaxf(f2, f3);
    float p3 = fmaxf(f3, f4);
    float p4 = fmaxf(f4, f5);
    float p5 = fmaxf(f5, f6);
    return make_float4(fmaxf(fmaxf(p0, p2), f4),
                       fmaxf(fmaxf(p1, p3), f5),
                       fmaxf(fmaxf(p2, p4), f6),
                       fmaxf(fmaxf(p3, p5), f7));
}

__device__ __forceinline__ void cp16(float* dst_s, const float* src_g) {
    unsigned d = (unsigned)__cvta_generic_to_shared(dst_s);
    asm volatile("cp.async.cg.shared.global [%0], [%1], 16;\n" :: "r"(d), "l"(src_g) : "memory");
}
__device__ __forceinline__ void cp_commit() {
    asm volatile("cp.async.commit_group;\n" ::: "memory");
}
template <int N>
__device__ __forceinline__ void cp_wait() {
    asm volatile("cp.async.wait_group %0;\n" :: "n"(N) : "memory");
}

__global__ __launch_bounds__(TPB)
void dilation5x5_kernel(const float* __restrict__ in, float* __restrict__ out) {
    __shared__ __align__(16) float sb[STAGES][SROW];

    const int tid  = threadIdx.x;
    const int bx   = blockIdx.x;
    const int base = bx * BCOLS;                 // first output col of this block
    const int y0   = blockIdx.y * RPB;           // y0 % 256 == 0 -> stage math folds
    const size_t plane = (size_t)blockIdx.z * (size_t)H * (size_t)W;
    const float* __restrict__ pin  = in  + plane;
    float* __restrict__       pout = out + plane;
    const bool lastx = (bx == (int)gridDim.x - 1);

    // Prefill image-edge halo cells (never written by cp.async for edge blocks).
    if (tid < STAGES * 4) {
        int s = tid >> 2, j = tid & 3;
        if (bx == 0) sb[s][j] = NEGV;
        if (lastx)   sb[s][1028 + j] = NEGV;
    }
    __syncthreads();

    // Produce one input row into its stage buffer. Window: cols [base-4, base+1028).
    // Thread t loads 16B chunk t (smem idx 4t); threads 0/1 load the 2 tail chunks.
    auto produce = [&](int r) {
        const int st = r & (STAGES - 1);
        float* dst = &sb[st][4 * tid];
        if ((unsigned)r < (unsigned)H) {
            const float* src = pin + (size_t)r * W + (base - 4 + 4 * tid);
            if (bx > 0 || tid > 0) cp16(dst, src);                 // chunk 0 OOB only at bx==0
            if (tid == 0)          cp16(&sb[st][1024], src + 1024); // cols base+1020..1023
            if (tid == 1 && !lastx) cp16(&sb[st][1028], src + 1024); // cols base+1024..1027
        } else {
            // OOB row: NEGV pad (same mapping; STS, not cp.async)
            float4 nv = make_float4(NEGV, NEGV, NEGV, NEGV);
            *reinterpret_cast<float4*>(dst) = nv;
            if (tid == 0) *reinterpret_cast<float4*>(&sb[st][1024]) = nv;
            if (tid == 1) *reinterpret_cast<float4*>(&sb[st][1028]) = nv;
        }
        cp_commit();   // one group per row (possibly empty/STS-only: still counted)
    };

    // Horizontal 5-max of a staged row for this thread's 4 output cols.
    auto readrow = [&](int r) -> float4 {
        const int st = r & (STAGES - 1);
        float2 l = *reinterpret_cast<const float2*>(&sb[st][4 * tid + 2]);  // col0-2..col0-1
        float4 c = *reinterpret_cast<const float4*>(&sb[st][4 * tid + 4]);  // col0..col0+3
        float2 rr = *reinterpret_cast<const float2*>(&sb[st][4 * tid + 8]); // col0+4..col0+5
        return hmax(l, c, rr);
    };

    // Prologue: stage rows y0-2 .. y0+5, then build the hmax ring for y0-2..y0+1.
    #pragma unroll
    for (int r = y0 - 2; r < y0 + 6; ++r) produce(r);
    cp_wait<4>();          // rows y0-2..y0+1 resident
    __syncthreads();

    float4 h0 = readrow(y0 - 2);
    float4 h1 = readrow(y0 - 1);
    float4 h2 = readrow(y0);
    float4 h3 = readrow(y0 + 1);

    float* po = pout + (size_t)y0 * W + base + 4 * tid;
    const int rmax = y0 + RPB + 1;   // last input row actually needed

    #pragma unroll 8
    for (int i = 0; i < RPB; ++i) {
        cp_wait<3>();            // row y0+2+i resident
        __syncthreads();

        float4 h4 = readrow(y0 + 2 + i);
        float4 o = max4(max4(max4(h0, h1), max4(h2, h3)), h4);
        __stcs(reinterpret_cast<float4*>(po), o);
        po += W;

        const int r = y0 + 6 + i;          // refill stage (r-8 fully consumed 4 iters ago)
        if (r <= rmax) produce(r);
        else           cp_commit();        // keep group counting uniform

        h0 = h1; h1 = h2; h2 = h3; h3 = h4;
    }
    cp_wait<0>();   // drain before exit
}

extern "C" void kernel_launch(void* const* d_in, const int* in_sizes, int n_in,
                              void* d_out, int out_size) {
    const float* image = (const float*)d_in[0];
    // d_in[1] is the all-ones 5x5 SE: neigh offsets are 0, so this is exactly a
    // 5x5 sliding max with -1e4 padding (pad never beats interior values >= 0).
    float* out = (float*)d_out;

    dim3 block(TPB, 1, 1);
    dim3 grid(W / BCOLS, H / RPB, 24);   // 2 x 8 x 24 = 384 blocks -> one resident wave
    dilation5x5_kernel<<<grid, block>>>(image, out);
}